// round 2
// baseline (speedup 1.0000x reference)
#include <cuda_runtime.h>
#include <math.h>

#define SPLINE_ORDER 3
#define GRID_N   16
#define IN_DIM   64
#define OUT_DIM  64
#define BATCH    1024
#define NCOEF    (GRID_N + SPLINE_ORDER)   // 19

#define BT 32                // batch tile = warp lanes
#define OB 4                 // o-columns per block
#define THREADS 256
#define PITCH4 17            // float4 row pitch (16 data + 1 pad)

// packed[o][i][m] = float4(coef[o,i,m..m+3]);  64*64*16 float4 = 1 MB scratch.
__device__ float4 g_packed[OUT_DIM * IN_DIM * GRID_N];

__global__ void pack_coef_kernel(const float* __restrict__ coef) {
    int p = blockIdx.x * blockDim.x + threadIdx.x;
    if (p >= OUT_DIM * IN_DIM * GRID_N) return;
    int m  = p & (GRID_N - 1);
    int oi = p >> 4;
    const float* c = coef + oi * NCOEF + m;
    g_packed[p] = make_float4(c[0], c[1], c[2], c[3]);
}

__global__ __launch_bounds__(THREADS)
void kan_kernel(const float* __restrict__ x,
                const float* __restrict__ grid,
                float* __restrict__ out) {
    __shared__ float  xs[BT * 65];                 // x tile, pad 65 (odd stride)
    __shared__ float4 S4[OB * BT * PITCH4];        // results, [oo][b][i4] pitch 17

    const int b0 = (blockIdx.x & 31) * BT;         // 32 batch tiles
    const int o0 = (blockIdx.x >> 5) * OB;         // 16 o-chunks

    // Stage x[b0..b0+31, :] coalesced.
    for (int t = threadIdx.x; t < BT * IN_DIM; t += THREADS) {
        int bb = t >> 6, i = t & 63;
        xs[bb * 65 + i] = x[(b0 + bb) * IN_DIM + i];
    }
    __syncthreads();

    // Uniform-grid params (two independent loads).
    const float g3    = grid[SPLINE_ORDER];
    const float g4    = grid[SPLINE_ORDER + 1];
    const float inv_h = 1.0f / (g4 - g3);
    const float k6    = 1.0f / 6.0f;

    const int lane = threadIdx.x & 31;   // -> batch within tile
    const int warp = threadIdx.x >> 5;   // -> i-group (8 i's per warp)

    #pragma unroll
    for (int g = 0; g < 2; g++) {        // two float4 i-groups per warp
        const int ibase = warp * 8 + g * 4;

        // Closed-form uniform cubic B-spline weights for 4 consecutive i.
        float w0[4], w1[4], w2[4], w3[4];
        const float4* prow[4];
        #pragma unroll
        for (int j = 0; j < 4; j++) {
            const float xv = xs[lane * 65 + ibase + j];
            float t = (xv - g3) * inv_h;
            int i0 = (int)floorf(t);
            i0 = min(GRID_N - 1, max(0, i0));
            const float u  = t - (float)i0;
            const float om = 1.0f - u;
            const float u2 = u * u;
            w0[j] = om * om * om * k6;
            w3[j] = u2 * u * k6;
            w1[j] = fmaf(u2, fmaf(0.5f, u, -1.0f), 2.0f / 3.0f);   // (3u^3-6u^2+4)/6
            w2[j] = 1.0f - w0[j] - w1[j] - w3[j];
            prow[j] = g_packed + (size_t)(o0 * IN_DIM + ibase + j) * GRID_N + i0;
        }

        const int i4 = warp * 2 + g;     // float4 column index 0..15
        #pragma unroll
        for (int oo = 0; oo < OB; oo++) {
            // 4 independent LDG.128 from within one 256B row each (lanes=b).
            float4 c0 = prow[0][oo * (IN_DIM * GRID_N)];
            float4 c1 = prow[1][oo * (IN_DIM * GRID_N)];
            float4 c2 = prow[2][oo * (IN_DIM * GRID_N)];
            float4 c3 = prow[3][oo * (IN_DIM * GRID_N)];
            float4 r;
            r.x = fmaf(w3[0], c0.w, fmaf(w2[0], c0.z, fmaf(w1[0], c0.y, w0[0] * c0.x)));
            r.y = fmaf(w3[1], c1.w, fmaf(w2[1], c1.z, fmaf(w1[1], c1.y, w0[1] * c1.x)));
            r.z = fmaf(w3[2], c2.w, fmaf(w2[2], c2.z, fmaf(w1[2], c2.y, w0[2] * c2.x)));
            r.w = fmaf(w3[3], c3.w, fmaf(w2[3], c3.z, fmaf(w1[3], c3.y, w0[3] * c3.x)));
            S4[(oo * BT + lane) * PITCH4 + i4] = r;   // STS.128, phase-conflict-free
        }
    }
    __syncthreads();

    // Transposed store: 2048 float4s, 8 per thread, fully coalesced STG.128.
    #pragma unroll
    for (int k = 0; k < 8; k++) {
        int t  = threadIdx.x + k * THREADS;
        int i4 = t & 15;
        int oo = (t >> 4) & 3;
        int bb = t >> 6;
        float4 v = S4[(oo * BT + bb) * PITCH4 + i4];  // LDS.128, conflict-free
        reinterpret_cast<float4*>(out)[((size_t)(b0 + bb) * OUT_DIM + (o0 + oo)) * (IN_DIM / 4) + i4] = v;
    }
}

extern "C" void kernel_launch(void* const* d_in, const int* in_sizes, int n_in,
                              void* d_out, int out_size) {
    const float* x    = (const float*)d_in[0];
    const float* coef = (const float*)d_in[1];
    const float* grid = (const float*)d_in[2];
    float* out        = (float*)d_out;

    pack_coef_kernel<<<(OUT_DIM * IN_DIM * GRID_N + 255) / 256, 256>>>(coef);
    kan_kernel<<<(BATCH / BT) * (OUT_DIM / OB), THREADS>>>(x, grid, out);
}